// round 1
// baseline (speedup 1.0000x reference)
#include <cuda_runtime.h>
#include <math.h>

#define NN   20000
#define EE   320000
#define FIN  386
#define HID  256
#define NOUT 2

#define SCAN_BLK 1024
#define SCAN_NBLK ((NN + SCAN_BLK - 1) / SCAN_BLK)   // 20

// ---------------- scratch (no allocations allowed) ----------------
__device__ int   g_counts[NN];
__device__ int   g_rowstart[NN + 1];
__device__ int   g_cursor[NN];
__device__ int   g_blocksums[SCAN_NBLK];
__device__ int   g_csr_src[EE];
__device__ float g_dis[NN];
__device__ float g_xw[(size_t)NN * HID];   // x @ W1
__device__ float g_h[(size_t)NN * HID];    // relu(aggregated + b1)
__device__ float g_h2[NN * NOUT];          // h @ W2

// ---------------- small helpers ----------------
__device__ __forceinline__ float4 f4_fma(const float4 a, const float s, float4 c) {
    c.x = fmaf(a.x, s, c.x);
    c.y = fmaf(a.y, s, c.y);
    c.z = fmaf(a.z, s, c.z);
    c.w = fmaf(a.w, s, c.w);
    return c;
}
__device__ __forceinline__ float4 f4_mul(const float4 a, const float s) {
    return make_float4(a.x * s, a.y * s, a.z * s, a.w * s);
}
__device__ __forceinline__ float4 f4_add(const float4 a, const float4 b) {
    return make_float4(a.x + b.x, a.y + b.y, a.z + b.z, a.w + b.w);
}
__device__ __forceinline__ float4 f4_relu(float4 a) {
    a.x = fmaxf(a.x, 0.f); a.y = fmaxf(a.y, 0.f);
    a.z = fmaxf(a.z, 0.f); a.w = fmaxf(a.w, 0.f);
    return a;
}

// ---------------- CSR build ----------------
__global__ void k_init_counts() {
    int i = blockIdx.x * blockDim.x + threadIdx.x;
    if (i < NN) g_counts[i] = 0;
}

__global__ void k_count(const int* __restrict__ dst) {
    int e = blockIdx.x * blockDim.x + threadIdx.x;
    if (e < EE) atomicAdd(&g_counts[dst[e]], 1);
}

// per-block inclusive scan (Hillis-Steele), writes inclusive values + block sums
__global__ void k_scan1() {
    __shared__ int s[SCAN_BLK];
    int t = threadIdx.x;
    int i = blockIdx.x * SCAN_BLK + t;
    int v = (i < NN) ? g_counts[i] : 0;
    s[t] = v;
    __syncthreads();
    #pragma unroll
    for (int off = 1; off < SCAN_BLK; off <<= 1) {
        int add = (t >= off) ? s[t - off] : 0;
        __syncthreads();
        s[t] += add;
        __syncthreads();
    }
    if (i < NN) g_rowstart[i] = s[t];       // inclusive, no block offset yet
    if (t == SCAN_BLK - 1) g_blocksums[blockIdx.x] = s[t];
}

// exclusive scan of the (tiny) block sums
__global__ void k_scan2() {
    if (threadIdx.x == 0) {
        int acc = 0;
        for (int j = 0; j < SCAN_NBLK; j++) {
            int c = g_blocksums[j];
            g_blocksums[j] = acc;
            acc += c;
        }
        g_rowstart[NN] = acc;   // == EE
    }
}

// finalize exclusive row_start, init cursor, compute dis = rsqrt(deg)
__global__ void k_scan3() {
    int i = blockIdx.x * blockDim.x + threadIdx.x;
    if (i >= NN) return;
    int incl = g_rowstart[i];
    int cnt  = g_counts[i];
    int excl = incl - cnt + g_blocksums[i / SCAN_BLK];
    g_rowstart[i] = excl;
    g_cursor[i]   = excl;
    g_dis[i]      = rsqrtf((float)cnt + 1.0f);   // self-loop included
}

__global__ void k_fill(const int* __restrict__ src, const int* __restrict__ dst) {
    int e = blockIdx.x * blockDim.x + threadIdx.x;
    if (e >= EE) return;
    int d = dst[e];
    int p = atomicAdd(&g_cursor[d], 1);
    g_csr_src[p] = src[e];
}

// ---------------- GEMM1: g_xw = x @ W1  (fp32, tiled SIMT) ----------------
#define BM 64
#define BN 64
#define BK 16
__global__ void k_gemm1(const float* __restrict__ A, const float* __restrict__ B) {
    __shared__ float As[BK][BM];
    __shared__ float Bs[BK][BN];
    int t  = threadIdx.x;          // 256
    int tx = t & 15;               // 0..15
    int ty = t >> 4;               // 0..15
    int rowBase = blockIdx.y * BM;
    int colBase = blockIdx.x * BN;

    float acc[4][4] = {};

    for (int k0 = 0; k0 < FIN; k0 += BK) {
        // load A tile: BM x BK = 1024 elems, 4 per thread
        #pragma unroll
        for (int i = 0; i < 4; i++) {
            int idx = t + i * 256;
            int r = idx >> 4;          // 0..63
            int c = idx & 15;          // 0..15
            int gr = rowBase + r;
            int gc = k0 + c;
            As[c][r] = (gr < NN && gc < FIN) ? A[(size_t)gr * FIN + gc] : 0.f;
        }
        // load B tile: BK x BN = 1024 elems, 4 per thread
        #pragma unroll
        for (int i = 0; i < 4; i++) {
            int idx = t + i * 256;
            int r = idx >> 6;          // 0..15
            int c = idx & 63;          // 0..63
            int gk = k0 + r;
            Bs[r][c] = (gk < FIN) ? B[(size_t)gk * HID + colBase + c] : 0.f;
        }
        __syncthreads();

        #pragma unroll
        for (int k = 0; k < BK; k++) {
            float a[4], b[4];
            #pragma unroll
            for (int i = 0; i < 4; i++) a[i] = As[k][ty * 4 + i];
            #pragma unroll
            for (int j = 0; j < 4; j++) b[j] = Bs[k][tx * 4 + j];
            #pragma unroll
            for (int i = 0; i < 4; i++)
                #pragma unroll
                for (int j = 0; j < 4; j++)
                    acc[i][j] = fmaf(a[i], b[j], acc[i][j]);
        }
        __syncthreads();
    }

    #pragma unroll
    for (int i = 0; i < 4; i++) {
        int row = rowBase + ty * 4 + i;
        if (row >= NN) continue;
        #pragma unroll
        for (int j = 0; j < 4; j++) {
            g_xw[(size_t)row * HID + colBase + tx * 4 + j] = acc[i][j];
        }
    }
}

// ---------------- agg1: h = relu( sum_in xw[s]*dis[s]*dis[n] + xw[n]*dis[n]^2 + b1 )
// one warp per node; lane covers 8 floats (2 float4) of the 256-wide row
__global__ void k_agg1(const float* __restrict__ b1) {
    int gw   = (blockIdx.x * blockDim.x + threadIdx.x) >> 5;
    int lane = threadIdx.x & 31;
    if (gw >= NN) return;
    int n = gw;
    float dn = g_dis[n];

    const float4* xw4 = (const float4*)g_xw;
    size_t base = (size_t)n * (HID / 4);

    float sn = dn * dn;
    float4 acc0 = f4_mul(xw4[base + lane], sn);
    float4 acc1 = f4_mul(xw4[base + 32 + lane], sn);

    int rs = g_rowstart[n];
    int re = g_rowstart[n + 1];
    for (int p = rs; p < re; p++) {
        int s = g_csr_src[p];
        float w = g_dis[s] * dn;
        size_t sb = (size_t)s * (HID / 4);
        acc0 = f4_fma(xw4[sb + lane], w, acc0);
        acc1 = f4_fma(xw4[sb + 32 + lane], w, acc1);
    }

    const float4* b14 = (const float4*)b1;
    acc0 = f4_relu(f4_add(acc0, b14[lane]));
    acc1 = f4_relu(f4_add(acc1, b14[32 + lane]));

    float4* h4 = (float4*)g_h;
    h4[base + lane]      = acc0;
    h4[base + 32 + lane] = acc1;
}

// ---------------- GEMM2: g_h2 = h @ W2  (warp per node, OUT=2) ----------------
__global__ void k_gemm2(const float* __restrict__ W2) {
    __shared__ float sW[HID * NOUT];
    for (int i = threadIdx.x; i < HID * NOUT; i += blockDim.x) sW[i] = W2[i];
    __syncthreads();

    int gw   = (blockIdx.x * blockDim.x + threadIdx.x) >> 5;
    int lane = threadIdx.x & 31;
    if (gw >= NN) return;
    int n = gw;

    const float4* h4 = (const float4*)g_h;
    size_t base = (size_t)n * (HID / 4);
    float s0 = 0.f, s1 = 0.f;
    #pragma unroll
    for (int i = 0; i < 2; i++) {
        float4 v = h4[base + i * 32 + lane];
        int f = (i * 32 + lane) * 4;
        s0 = fmaf(v.x, sW[(f + 0) * 2 + 0], s0);
        s1 = fmaf(v.x, sW[(f + 0) * 2 + 1], s1);
        s0 = fmaf(v.y, sW[(f + 1) * 2 + 0], s0);
        s1 = fmaf(v.y, sW[(f + 1) * 2 + 1], s1);
        s0 = fmaf(v.z, sW[(f + 2) * 2 + 0], s0);
        s1 = fmaf(v.z, sW[(f + 2) * 2 + 1], s1);
        s0 = fmaf(v.w, sW[(f + 3) * 2 + 0], s0);
        s1 = fmaf(v.w, sW[(f + 3) * 2 + 1], s1);
    }
    #pragma unroll
    for (int off = 16; off > 0; off >>= 1) {
        s0 += __shfl_down_sync(0xffffffffu, s0, off);
        s1 += __shfl_down_sync(0xffffffffu, s1, off);
    }
    if (lane == 0) {
        g_h2[n * 2 + 0] = s0;
        g_h2[n * 2 + 1] = s1;
    }
}

// ---------------- agg2 + tanh: out = tanh( agg(h2) + b2 ) ----------------
__global__ void k_agg2(const float* __restrict__ b2, float* __restrict__ out) {
    int n = blockIdx.x * blockDim.x + threadIdx.x;
    if (n >= NN) return;
    float dn = g_dis[n];
    const float2* h2 = (const float2*)g_h2;
    float2 hn = h2[n];
    float sn = dn * dn;
    float a0 = hn.x * sn;
    float a1 = hn.y * sn;
    int rs = g_rowstart[n];
    int re = g_rowstart[n + 1];
    for (int p = rs; p < re; p++) {
        int s = g_csr_src[p];
        float w = g_dis[s] * dn;
        float2 v = h2[s];
        a0 = fmaf(v.x, w, a0);
        a1 = fmaf(v.y, w, a1);
    }
    out[n * 2 + 0] = tanhf(a0 + b2[0]);
    out[n * 2 + 1] = tanhf(a1 + b2[1]);
}

// ---------------- launch ----------------
extern "C" void kernel_launch(void* const* d_in, const int* in_sizes, int n_in,
                              void* d_out, int out_size) {
    const float* x   = (const float*)d_in[0];
    const int*   src = (const int*)  d_in[1];
    const int*   dst = (const int*)  d_in[2];
    const float* W1  = (const float*)d_in[3];
    const float* b1  = (const float*)d_in[4];
    const float* W2  = (const float*)d_in[5];
    const float* b2  = (const float*)d_in[6];
    float* out = (float*)d_out;

    (void)in_sizes; (void)n_in; (void)out_size;

    // CSR build + degree
    k_init_counts<<<(NN + 255) / 256, 256>>>();
    k_count<<<(EE + 255) / 256, 256>>>(dst);
    k_scan1<<<SCAN_NBLK, SCAN_BLK>>>();
    k_scan2<<<1, 32>>>();
    k_scan3<<<(NN + 255) / 256, 256>>>();
    k_fill<<<(EE + 255) / 256, 256>>>(src, dst);

    // layer 1
    dim3 g1(HID / BN, (NN + BM - 1) / BM);
    k_gemm1<<<g1, 256>>>(x, W1);
    k_agg1<<<(NN * 32 + 255) / 256, 256>>>(b1);

    // layer 2
    k_gemm2<<<(NN * 32 + 255) / 256, 256>>>(W2);
    k_agg2<<<(NN + 255) / 256, 256>>>(b2, out);
}

// round 3
// speedup vs baseline: 1.5185x; 1.5185x over previous
#include <cuda_runtime.h>
#include <math.h>

#define NN   20000
#define EE   320000
#define FIN  386
#define HID  256
#define NOUT 2

#define SCAN_BLK 1024
#define SCAN_NBLK ((NN + SCAN_BLK - 1) / SCAN_BLK)   // 20

// ---------------- scratch (no allocations allowed) ----------------
__device__ int   g_counts[NN];
__device__ int   g_rowstart[NN + 1];
__device__ int   g_cursor[NN];
__device__ int   g_blocksums[SCAN_NBLK];
__device__ int   g_csr_src[EE];
__device__ float g_dis[NN];
__device__ float g_xw[(size_t)NN * HID];   // x @ W1
__device__ float g_h[(size_t)NN * HID];    // relu(aggregated + b1)
__device__ float g_h2[NN * NOUT];          // h @ W2

// ---------------- small helpers ----------------
__device__ __forceinline__ float4 f4_fma(const float4 a, const float s, float4 c) {
    c.x = fmaf(a.x, s, c.x);
    c.y = fmaf(a.y, s, c.y);
    c.z = fmaf(a.z, s, c.z);
    c.w = fmaf(a.w, s, c.w);
    return c;
}
__device__ __forceinline__ float4 f4_mul(const float4 a, const float s) {
    return make_float4(a.x * s, a.y * s, a.z * s, a.w * s);
}
__device__ __forceinline__ float4 f4_add(const float4 a, const float4 b) {
    return make_float4(a.x + b.x, a.y + b.y, a.z + b.z, a.w + b.w);
}
__device__ __forceinline__ float4 f4_relu(float4 a) {
    a.x = fmaxf(a.x, 0.f); a.y = fmaxf(a.y, 0.f);
    a.z = fmaxf(a.z, 0.f); a.w = fmaxf(a.w, 0.f);
    return a;
}
__device__ __forceinline__ unsigned f2tf32(float f) {
    unsigned r;
    asm("cvt.rna.tf32.f32 %0, %1;" : "=r"(r) : "f"(f));
    return r;
}

// ---------------- CSR build ----------------
__global__ void k_init_counts() {
    int i = blockIdx.x * blockDim.x + threadIdx.x;
    if (i < NN) g_counts[i] = 0;
}

__global__ void k_count(const int* __restrict__ dst) {
    int e = blockIdx.x * blockDim.x + threadIdx.x;
    if (e < EE) atomicAdd(&g_counts[dst[e]], 1);
}

// per-block inclusive scan (Hillis-Steele), writes inclusive values + block sums
__global__ void k_scan1() {
    __shared__ int s[SCAN_BLK];
    int t = threadIdx.x;
    int i = blockIdx.x * SCAN_BLK + t;
    int v = (i < NN) ? g_counts[i] : 0;
    s[t] = v;
    __syncthreads();
    #pragma unroll
    for (int off = 1; off < SCAN_BLK; off <<= 1) {
        int add = (t >= off) ? s[t - off] : 0;
        __syncthreads();
        s[t] += add;
        __syncthreads();
    }
    if (i < NN) g_rowstart[i] = s[t];       // inclusive, no block offset yet
    if (t == SCAN_BLK - 1) g_blocksums[blockIdx.x] = s[t];
}

// exclusive scan of the (tiny) block sums
__global__ void k_scan2() {
    if (threadIdx.x == 0) {
        int acc = 0;
        for (int j = 0; j < SCAN_NBLK; j++) {
            int c = g_blocksums[j];
            g_blocksums[j] = acc;
            acc += c;
        }
        g_rowstart[NN] = acc;   // == EE
    }
}

// finalize exclusive row_start, init cursor, compute dis = rsqrt(deg)
__global__ void k_scan3() {
    int i = blockIdx.x * blockDim.x + threadIdx.x;
    if (i >= NN) return;
    int incl = g_rowstart[i];
    int cnt  = g_counts[i];
    int excl = incl - cnt + g_blocksums[i / SCAN_BLK];
    g_rowstart[i] = excl;
    g_cursor[i]   = excl;
    g_dis[i]      = rsqrtf((float)cnt + 1.0f);   // self-loop included
}

__global__ void k_fill(const int* __restrict__ src, const int* __restrict__ dst) {
    int e = blockIdx.x * blockDim.x + threadIdx.x;
    if (e >= EE) return;
    int d = dst[e];
    int p = atomicAdd(&g_cursor[d], 1);
    g_csr_src[p] = src[e];
}

// ---------------- GEMM1 (tf32 tensor-core): g_xw = x @ W1 ----------------
// BM=128, BN=64, BK=32; 256 threads = 8 warps in a 4x2 grid; warp tile 32x32.
// mma.sync.aligned.m16n8k8.row.col.f32.tf32.tf32.f32
#define BM 128
#define BN 64
#define BK 32
#define ASTRIDE (BK + 1)   // 33 floats
#define BSTRIDE (BK + 1)

__global__ void __launch_bounds__(256, 2)
k_gemm1(const float* __restrict__ A, const float* __restrict__ B) {
    __shared__ float As[BM * ASTRIDE];   // As[row][k]
    __shared__ float Bs[BN * BSTRIDE];   // Bs[n][k]  (transposed W1 tile)

    const int t    = threadIdx.x;
    const int warp = t >> 5;
    const int lane = t & 31;
    const int wrow = (warp & 3) * 32;    // warp row offset in tile (0,32,64,96)
    const int wcol = (warp >> 2) * 32;   // warp col offset (0,32)

    const int rowBase = blockIdx.y * BM;
    const int colBase = blockIdx.x * BN;

    const int qrow = lane >> 2;          // 0..7
    const int qcol = lane & 3;           // 0..3

    float acc[2][4][4];
    #pragma unroll
    for (int mi = 0; mi < 2; mi++)
        #pragma unroll
        for (int ni = 0; ni < 4; ni++)
            #pragma unroll
            for (int c = 0; c < 4; c++) acc[mi][ni][c] = 0.f;

    for (int k0 = 0; k0 < FIN; k0 += BK) {
        // ---- load A tile: BM x BK as float2 (FIN=386: row stride 8B-aligned,
        //      k0 even so float2 granularity is always fully valid or invalid)
        #pragma unroll
        for (int i = 0; i < 8; i++) {
            int idx = t + i * 256;          // 0..2047
            int r = idx >> 4;               // 0..127
            int p = idx & 15;               // float2 pair 0..15
            int gr = rowBase + r;
            int gc = k0 + p * 2;
            float2 v = make_float2(0.f, 0.f);
            if (gr < NN && gc < FIN)
                v = *(const float2*)(A + (size_t)gr * FIN + gc);
            As[r * ASTRIDE + p * 2]     = v.x;
            As[r * ASTRIDE + p * 2 + 1] = v.y;
        }
        // ---- load B tile transposed: Bs[n][k] = W1[k0+k][colBase+n]
        //      thread reads coalesced along n, 32 k-rows x 64 n-cols = 2048 elems
        #pragma unroll
        for (int i = 0; i < 8; i++) {
            int idx = t + i * 256;
            int kk = idx >> 6;              // 0..31
            int n  = idx & 63;              // 0..63
            int gk = k0 + kk;
            float v = (gk < FIN) ? B[(size_t)gk * HID + colBase + n] : 0.f;
            Bs[n * BSTRIDE + kk] = v;
        }
        __syncthreads();

        #pragma unroll
        for (int ks = 0; ks < BK; ks += 8) {
            // A fragments for 2 m-tiles
            unsigned af[2][4];
            #pragma unroll
            for (int mi = 0; mi < 2; mi++) {
                int r0 = wrow + mi * 16 + qrow;
                af[mi][0] = f2tf32(As[(r0)     * ASTRIDE + ks + qcol]);
                af[mi][1] = f2tf32(As[(r0 + 8) * ASTRIDE + ks + qcol]);
                af[mi][2] = f2tf32(As[(r0)     * ASTRIDE + ks + qcol + 4]);
                af[mi][3] = f2tf32(As[(r0 + 8) * ASTRIDE + ks + qcol + 4]);
            }
            // B fragments for 4 n-tiles
            unsigned bf[4][2];
            #pragma unroll
            for (int ni = 0; ni < 4; ni++) {
                int n0 = wcol + ni * 8 + qrow;
                bf[ni][0] = f2tf32(Bs[n0 * BSTRIDE + ks + qcol]);
                bf[ni][1] = f2tf32(Bs[n0 * BSTRIDE + ks + qcol + 4]);
            }
            #pragma unroll
            for (int mi = 0; mi < 2; mi++)
                #pragma unroll
                for (int ni = 0; ni < 4; ni++) {
                    asm volatile(
                        "mma.sync.aligned.m16n8k8.row.col.f32.tf32.tf32.f32 "
                        "{%0,%1,%2,%3}, {%4,%5,%6,%7}, {%8,%9}, {%0,%1,%2,%3};"
                        : "+f"(acc[mi][ni][0]), "+f"(acc[mi][ni][1]),
                          "+f"(acc[mi][ni][2]), "+f"(acc[mi][ni][3])
                        : "r"(af[mi][0]), "r"(af[mi][1]), "r"(af[mi][2]), "r"(af[mi][3]),
                          "r"(bf[ni][0]), "r"(bf[ni][1]));
                }
        }
        __syncthreads();
    }

    // ---- store C (float2 per fragment row-half; col even -> 8B aligned)
    #pragma unroll
    for (int mi = 0; mi < 2; mi++) {
        #pragma unroll
        for (int ni = 0; ni < 4; ni++) {
            int col = colBase + wcol + ni * 8 + qcol * 2;
            int r0 = rowBase + wrow + mi * 16 + qrow;
            if (r0 < NN)
                *(float2*)(g_xw + (size_t)r0 * HID + col) =
                    make_float2(acc[mi][ni][0], acc[mi][ni][1]);
            int r1 = r0 + 8;
            if (r1 < NN)
                *(float2*)(g_xw + (size_t)r1 * HID + col) =
                    make_float2(acc[mi][ni][2], acc[mi][ni][3]);
        }
    }
}

// ---------------- agg1: h = relu( sum_in xw[s]*dis[s]*dis[n] + xw[n]*dis[n]^2 + b1 )
// one warp per node; lane covers 8 floats (2 float4) of the 256-wide row
__global__ void k_agg1(const float* __restrict__ b1) {
    int gw   = (blockIdx.x * blockDim.x + threadIdx.x) >> 5;
    int lane = threadIdx.x & 31;
    if (gw >= NN) return;
    int n = gw;
    float dn = g_dis[n];

    const float4* xw4 = (const float4*)g_xw;
    size_t base = (size_t)n * (HID / 4);

    float sn = dn * dn;
    float4 acc0 = f4_mul(xw4[base + lane], sn);
    float4 acc1 = f4_mul(xw4[base + 32 + lane], sn);

    int rs = g_rowstart[n];
    int re = g_rowstart[n + 1];
    for (int p = rs; p < re; p++) {
        int s = g_csr_src[p];
        float w = g_dis[s] * dn;
        size_t sb = (size_t)s * (HID / 4);
        acc0 = f4_fma(xw4[sb + lane], w, acc0);
        acc1 = f4_fma(xw4[sb + 32 + lane], w, acc1);
    }

    const float4* b14 = (const float4*)b1;
    acc0 = f4_relu(f4_add(acc0, b14[lane]));
    acc1 = f4_relu(f4_add(acc1, b14[32 + lane]));

    float4* h4 = (float4*)g_h;
    h4[base + lane]      = acc0;
    h4[base + 32 + lane] = acc1;
}

// ---------------- GEMM2: g_h2 = h @ W2  (warp per node, OUT=2) ----------------
__global__ void k_gemm2(const float* __restrict__ W2) {
    __shared__ float sW[HID * NOUT];
    for (int i = threadIdx.x; i < HID * NOUT; i += blockDim.x) sW[i] = W2[i];
    __syncthreads();

    int gw   = (blockIdx.x * blockDim.x + threadIdx.x) >> 5;
    int lane = threadIdx.x & 31;
    if (gw >= NN) return;
    int n = gw;

    const float4* h4 = (const float4*)g_h;
    size_t base = (size_t)n * (HID / 4);
    float s0 = 0.f, s1 = 0.f;
    #pragma unroll
    for (int i = 0; i < 2; i++) {
        float4 v = h4[base + i * 32 + lane];
        int f = (i * 32 + lane) * 4;
        s0 = fmaf(v.x, sW[(f + 0) * 2 + 0], s0);
        s1 = fmaf(v.x, sW[(f + 0) * 2 + 1], s1);
        s0 = fmaf(v.y, sW[(f + 1) * 2 + 0], s0);
        s1 = fmaf(v.y, sW[(f + 1) * 2 + 1], s1);
        s0 = fmaf(v.z, sW[(f + 2) * 2 + 0], s0);
        s1 = fmaf(v.z, sW[(f + 2) * 2 + 1], s1);
        s0 = fmaf(v.w, sW[(f + 3) * 2 + 0], s0);
        s1 = fmaf(v.w, sW[(f + 3) * 2 + 1], s1);
    }
    #pragma unroll
    for (int off = 16; off > 0; off >>= 1) {
        s0 += __shfl_down_sync(0xffffffffu, s0, off);
        s1 += __shfl_down_sync(0xffffffffu, s1, off);
    }
    if (lane == 0) {
        g_h2[n * 2 + 0] = s0;
        g_h2[n * 2 + 1] = s1;
    }
}

// ---------------- agg2 + tanh: out = tanh( agg(h2) + b2 ) ----------------
__global__ void k_agg2(const float* __restrict__ b2, float* __restrict__ out) {
    int n = blockIdx.x * blockDim.x + threadIdx.x;
    if (n >= NN) return;
    float dn = g_dis[n];
    const float2* h2 = (const float2*)g_h2;
    float2 hn = h2[n];
    float sn = dn * dn;
    float a0 = hn.x * sn;
    float a1 = hn.y * sn;
    int rs = g_rowstart[n];
    int re = g_rowstart[n + 1];
    for (int p = rs; p < re; p++) {
        int s = g_csr_src[p];
        float w = g_dis[s] * dn;
        float2 v = h2[s];
        a0 = fmaf(v.x, w, a0);
        a1 = fmaf(v.y, w, a1);
    }
    out[n * 2 + 0] = tanhf(a0 + b2[0]);
    out[n * 2 + 1] = tanhf(a1 + b2[1]);
}

// ---------------- launch ----------------
extern "C" void kernel_launch(void* const* d_in, const int* in_sizes, int n_in,
                              void* d_out, int out_size) {
    const float* x   = (const float*)d_in[0];
    const int*   src = (const int*)  d_in[1];
    const int*   dst = (const int*)  d_in[2];
    const float* W1  = (const float*)d_in[3];
    const float* b1  = (const float*)d_in[4];
    const float* W2  = (const float*)d_in[5];
    const float* b2  = (const float*)d_in[6];
    float* out = (float*)d_out;

    (void)in_sizes; (void)n_in; (void)out_size;

    // CSR build + degree
    k_init_counts<<<(NN + 255) / 256, 256>>>();
    k_count<<<(EE + 255) / 256, 256>>>(dst);
    k_scan1<<<SCAN_NBLK, SCAN_BLK>>>();
    k_scan2<<<1, 32>>>();
    k_scan3<<<(NN + 255) / 256, 256>>>();
    k_fill<<<(EE + 255) / 256, 256>>>(src, dst);

    // layer 1
    dim3 g1(HID / BN, (NN + BM - 1) / BM);
    k_gemm1<<<g1, 256>>>(x, W1);
    k_agg1<<<(NN * 32 + 255) / 256, 256>>>(b1);

    // layer 2
    k_gemm2<<<(NN * 32 + 255) / 256, 256>>>(W2);
    k_agg2<<<(NN + 255) / 256, 256>>>(b2, out);
}